// round 2
// baseline (speedup 1.0000x reference)
#include <cuda_runtime.h>
#include <cuda_bf16.h>
#include <math.h>

// Problem constants
#define B_    2
#define S_    2048
#define H_    32
#define D_    128
#define DIM_  4096
#define ADL_  10

// ---------------- scratch (device globals; no allocation allowed) -----------
__device__ float g_Q [(size_t)B_ * S_ * DIM_];
__device__ float g_K [(size_t)B_ * S_ * DIM_];
__device__ float g_V [(size_t)B_ * S_ * DIM_];
__device__ float g_AO[(size_t)B_ * S_ * DIM_];
__device__ float g_aK[ADL_ * DIM_];
__device__ float g_aV[ADL_ * DIM_];

// =============================================================================
// GEMM: C[M,N] = A[M,K] * B[N,K]^T   (both row-major, K-contiguous)
// 128x128 block tile, BK=16, 256 threads, 8x8 per-thread micro tile.
// =============================================================================
#define BM 128
#define BN 128
#define BK 16
#define ASTR (BM + 4)

__global__ __launch_bounds__(256, 2)
void gemm_abt(const float* __restrict__ A, const float* __restrict__ Bm,
              float* __restrict__ C, int M, int N, int K)
{
    __shared__ float As[BK][ASTR];
    __shared__ float Bs[BK][ASTR];

    const int tid = threadIdx.x;
    const int tx  = tid & 15;        // 0..15  -> col group
    const int ty  = tid >> 4;        // 0..15  -> row group
    const int rowBase = blockIdx.y * BM;
    const int colBase = blockIdx.x * BN;

    const int lrow = tid >> 2;       // 0..63
    const int lk4  = (tid & 3) * 4;  // 0,4,8,12

    float acc[8][8];
#pragma unroll
    for (int i = 0; i < 8; i++)
#pragma unroll
        for (int j = 0; j < 8; j++) acc[i][j] = 0.f;

    for (int k0 = 0; k0 < K; k0 += BK) {
        // load A tile (transposed into smem), guard rows (M may be 10)
#pragma unroll
        for (int rr = 0; rr < 2; rr++) {
            int r  = lrow + rr * 64;
            int gr = rowBase + r;
            float4 v = make_float4(0.f, 0.f, 0.f, 0.f);
            if (gr < M) v = *(const float4*)(A + (size_t)gr * K + k0 + lk4);
            As[lk4 + 0][r] = v.x; As[lk4 + 1][r] = v.y;
            As[lk4 + 2][r] = v.z; As[lk4 + 3][r] = v.w;
        }
        // load B tile (N is always a multiple of 128 here)
#pragma unroll
        for (int rr = 0; rr < 2; rr++) {
            int r  = lrow + rr * 64;
            int gc = colBase + r;
            float4 v = *(const float4*)(Bm + (size_t)gc * K + k0 + lk4);
            Bs[lk4 + 0][r] = v.x; Bs[lk4 + 1][r] = v.y;
            Bs[lk4 + 2][r] = v.z; Bs[lk4 + 3][r] = v.w;
        }
        __syncthreads();

#pragma unroll
        for (int k = 0; k < BK; k++) {
            float a[8], b[8];
            *(float4*)&a[0] = *(const float4*)&As[k][ty * 8];
            *(float4*)&a[4] = *(const float4*)&As[k][ty * 8 + 4];
            *(float4*)&b[0] = *(const float4*)&Bs[k][tx * 8];
            *(float4*)&b[4] = *(const float4*)&Bs[k][tx * 8 + 4];
#pragma unroll
            for (int i = 0; i < 8; i++)
#pragma unroll
                for (int j = 0; j < 8; j++)
                    acc[i][j] = fmaf(a[i], b[j], acc[i][j]);
        }
        __syncthreads();
    }

#pragma unroll
    for (int i = 0; i < 8; i++) {
        int gr = rowBase + ty * 8 + i;
        if (gr >= M) continue;
        float* cp = C + (size_t)gr * N + colBase + tx * 8;
        *(float4*)cp       = make_float4(acc[i][0], acc[i][1], acc[i][2], acc[i][3]);
        *(float4*)(cp + 4) = make_float4(acc[i][4], acc[i][5], acc[i][6], acc[i][7]);
    }
}

// =============================================================================
// RoPE (interleaved pairs), in-place on [B,S,H,D]
// =============================================================================
__global__ void rope_kernel(float* __restrict__ t,
                            const float* __restrict__ cosp,
                            const float* __restrict__ sinp, int total)
{
    int idx = blockIdx.x * blockDim.x + threadIdx.x;   // pair index
    if (idx >= total) return;
    int i = idx & 63;                     // pair within head
    int s = (idx >> 11) & (S_ - 1);       // idx / (64*H) % S
    float2 v = *(float2*)(t + (size_t)idx * 2);
    float c  = cosp[s * 64 + i];
    float sn = sinp[s * 64 + i];
    float2 o;
    o.x = v.x * c - v.y * sn;
    o.y = v.x * sn + v.y * c;
    *(float2*)(t + (size_t)idx * 2) = o;
}

// =============================================================================
// Causal flash attention: Q,K,V layout [B,S,H*D]; per block: (qtile, h, b)
// BQ=64 queries, BK tiles of 64 keys, fp32 online softmax.
// =============================================================================
#define FQS 132   // row stride for Q/K/V tiles in smem
#define FPS 68    // row stride for P tile
#define FLASH_SMEM ((3 * 64 * FQS + 64 * FPS) * 4)

__global__ __launch_bounds__(256, 1)
void flash_kernel(const float* __restrict__ Q, const float* __restrict__ K,
                  const float* __restrict__ V, float* __restrict__ O)
{
    extern __shared__ float fsm[];
    float* Qs = fsm;
    float* Ks = Qs + 64 * FQS;
    float* Vs = Ks + 64 * FQS;
    float* Ps = Vs + 64 * FQS;

    const int qt = blockIdx.x;
    const int h  = blockIdx.y;
    const int b  = blockIdx.z;
    const int tid = threadIdx.x;
    const int tx  = tid & 15;
    const int ty  = tid >> 4;

    const float* Qbase = Q + ((size_t)(b * S_) + qt * 64) * DIM_ + h * D_;

    // load Q tile once
#pragma unroll
    for (int it = 0; it < 8; it++) {
        int idx = tid + it * 256;
        int r  = idx >> 5;
        int dq = (idx & 31) * 4;
        *(float4*)&Qs[r * FQS + dq] = *(const float4*)(Qbase + (size_t)r * DIM_ + dq);
    }

    float m[4], l[4], o[4][8];
#pragma unroll
    for (int i = 0; i < 4; i++) {
        m[i] = -1e30f; l[i] = 0.f;
#pragma unroll
        for (int c = 0; c < 8; c++) o[i][c] = 0.f;
    }
    const int qrow0 = qt * 64 + ty * 4;
    const float scale = 0.08838834764831845f;   // 1/sqrt(128)

    for (int kt = 0; kt <= qt; kt++) {
        __syncthreads();
        const float* Kbase = K + ((size_t)(b * S_) + kt * 64) * DIM_ + h * D_;
        const float* Vbase = V + ((size_t)(b * S_) + kt * 64) * DIM_ + h * D_;
#pragma unroll
        for (int it = 0; it < 8; it++) {
            int idx = tid + it * 256;
            int r  = idx >> 5;
            int dq = (idx & 31) * 4;
            *(float4*)&Ks[r * FQS + dq] = *(const float4*)(Kbase + (size_t)r * DIM_ + dq);
            *(float4*)&Vs[r * FQS + dq] = *(const float4*)(Vbase + (size_t)r * DIM_ + dq);
        }
        __syncthreads();

        // ---- scores: S = Q * K^T (4x4 per thread) ----
        float s[4][4];
#pragma unroll
        for (int i = 0; i < 4; i++)
#pragma unroll
            for (int j = 0; j < 4; j++) s[i][j] = 0.f;

#pragma unroll 8
        for (int d4 = 0; d4 < 32; d4++) {
            float4 qv[4], kv[4];
#pragma unroll
            for (int i = 0; i < 4; i++)
                qv[i] = *(const float4*)&Qs[(ty * 4 + i) * FQS + d4 * 4];
#pragma unroll
            for (int j = 0; j < 4; j++)
                kv[j] = *(const float4*)&Ks[(tx * 4 + j) * FQS + d4 * 4];
#pragma unroll
            for (int i = 0; i < 4; i++)
#pragma unroll
                for (int j = 0; j < 4; j++) {
                    s[i][j] = fmaf(qv[i].x, kv[j].x, s[i][j]);
                    s[i][j] = fmaf(qv[i].y, kv[j].y, s[i][j]);
                    s[i][j] = fmaf(qv[i].z, kv[j].z, s[i][j]);
                    s[i][j] = fmaf(qv[i].w, kv[j].w, s[i][j]);
                }
        }

        const bool diag = (kt == qt);
        float rscale[4];
#pragma unroll
        for (int i = 0; i < 4; i++) {
            int qg = qrow0 + i;
            float rmax = -1e30f;
#pragma unroll
            for (int j = 0; j < 4; j++) {
                float sv = s[i][j] * scale;
                if (diag && (kt * 64 + tx * 4 + j) > qg) sv = -1e30f;
                s[i][j] = sv;
                rmax = fmaxf(rmax, sv);
            }
#pragma unroll
            for (int off = 8; off; off >>= 1)
                rmax = fmaxf(rmax, __shfl_xor_sync(0xffffffffu, rmax, off, 16));
            float mnew = fmaxf(m[i], rmax);
            float sc   = __expf(m[i] - mnew);
            float rsum = 0.f;
#pragma unroll
            for (int j = 0; j < 4; j++) {
                float p = __expf(s[i][j] - mnew);
                s[i][j] = p;
                rsum += p;
            }
#pragma unroll
            for (int off = 8; off; off >>= 1)
                rsum += __shfl_xor_sync(0xffffffffu, rsum, off, 16);
            l[i] = l[i] * sc + rsum;
            m[i] = mnew;
            rscale[i] = sc;
            *(float4*)&Ps[(ty * 4 + i) * FPS + tx * 4] =
                make_float4(s[i][0], s[i][1], s[i][2], s[i][3]);
        }
        __syncwarp();

        // ---- PV: O += P * V  (rows ty*4+i, cols tx*8..tx*8+7) ----
#pragma unroll
        for (int i = 0; i < 4; i++)
#pragma unroll
            for (int c = 0; c < 8; c++) o[i][c] *= rscale[i];

#pragma unroll 4
        for (int j4 = 0; j4 < 16; j4++) {
            float4 p4[4];
#pragma unroll
            for (int i = 0; i < 4; i++)
                p4[i] = *(const float4*)&Ps[(ty * 4 + i) * FPS + j4 * 4];
#pragma unroll
            for (int jj = 0; jj < 4; jj++) {
                float4 v0 = *(const float4*)&Vs[(j4 * 4 + jj) * FQS + tx * 8];
                float4 v1 = *(const float4*)&Vs[(j4 * 4 + jj) * FQS + tx * 8 + 4];
#pragma unroll
                for (int i = 0; i < 4; i++) {
                    float p = (jj == 0) ? p4[i].x : (jj == 1) ? p4[i].y :
                              (jj == 2) ? p4[i].z : p4[i].w;
                    o[i][0] = fmaf(p, v0.x, o[i][0]);
                    o[i][1] = fmaf(p, v0.y, o[i][1]);
                    o[i][2] = fmaf(p, v0.z, o[i][2]);
                    o[i][3] = fmaf(p, v0.w, o[i][3]);
                    o[i][4] = fmaf(p, v1.x, o[i][4]);
                    o[i][5] = fmaf(p, v1.y, o[i][5]);
                    o[i][6] = fmaf(p, v1.z, o[i][6]);
                    o[i][7] = fmaf(p, v1.w, o[i][7]);
                }
            }
        }
    }

    float* Obase = O + ((size_t)(b * S_) + qt * 64) * DIM_ + h * D_;
#pragma unroll
    for (int i = 0; i < 4; i++) {
        float inv = 1.0f / l[i];
        float* op = Obase + (size_t)(ty * 4 + i) * DIM_ + tx * 8;
        *(float4*)op       = make_float4(o[i][0] * inv, o[i][1] * inv,
                                         o[i][2] * inv, o[i][3] * inv);
        *(float4*)(op + 4) = make_float4(o[i][4] * inv, o[i][5] * inv,
                                         o[i][6] * inv, o[i][7] * inv);
    }
}

// =============================================================================
// Adapter attention: one warp per (b,s,h); 10 keys, no mask, no rope on aK.
// Adds tanh(gate[h]) * softmax(q aK^T / sqrt(d)) aV into O (RMW).
// =============================================================================
__global__ void adapter_attn(const float* __restrict__ Q,
                             const float* __restrict__ aK,
                             const float* __restrict__ aV,
                             const float* __restrict__ gate,
                             float* __restrict__ O)
{
    int gw   = (blockIdx.x * blockDim.x + threadIdx.x) >> 5;
    int lane = threadIdx.x & 31;
    int h = gw & (H_ - 1);
    int s = (gw >> 5) & (S_ - 1);
    int b = gw >> 16;

    const float* q = Q + ((size_t)(b * S_ + s)) * DIM_ + h * D_;
    float4 qv = *(const float4*)(q + lane * 4);

    const float scale = 0.08838834764831845f;
    float sc[ADL_];
#pragma unroll
    for (int t = 0; t < ADL_; t++) {
        float4 kv = *(const float4*)(aK + t * DIM_ + h * D_ + lane * 4);
        float d = qv.x * kv.x + qv.y * kv.y + qv.z * kv.z + qv.w * kv.w;
#pragma unroll
        for (int off = 16; off; off >>= 1)
            d += __shfl_xor_sync(0xffffffffu, d, off);
        sc[t] = d * scale;
    }
    float mx = sc[0];
#pragma unroll
    for (int t = 1; t < ADL_; t++) mx = fmaxf(mx, sc[t]);
    float sum = 0.f;
#pragma unroll
    for (int t = 0; t < ADL_; t++) { sc[t] = __expf(sc[t] - mx); sum += sc[t]; }
    float inv = 1.0f / sum;
    float g = tanhf(gate[h]);

    float4 acc = make_float4(0.f, 0.f, 0.f, 0.f);
#pragma unroll
    for (int t = 0; t < ADL_; t++) {
        float4 vv = *(const float4*)(aV + t * DIM_ + h * D_ + lane * 4);
        float p = sc[t] * inv;
        acc.x = fmaf(p, vv.x, acc.x);
        acc.y = fmaf(p, vv.y, acc.y);
        acc.z = fmaf(p, vv.z, acc.z);
        acc.w = fmaf(p, vv.w, acc.w);
    }
    float* op = O + ((size_t)(b * S_ + s)) * DIM_ + h * D_ + lane * 4;
    float4 cur = *(float4*)op;
    cur.x += g * acc.x; cur.y += g * acc.y;
    cur.z += g * acc.z; cur.w += g * acc.w;
    *(float4*)op = cur;
}

// =============================================================================
// launch
// =============================================================================
extern "C" void kernel_launch(void* const* d_in, const int* in_sizes, int n_in,
                              void* d_out, int out_size)
{
    const float* x       = (const float*)d_in[0];
    const float* wq      = (const float*)d_in[1];
    const float* wk      = (const float*)d_in[2];
    const float* wv      = (const float*)d_in[3];
    const float* wo      = (const float*)d_in[4];
    const float* gate    = (const float*)d_in[5];
    const float* adapter = (const float*)d_in[6];
    const float* fcos    = (const float*)d_in[7];
    const float* fsin    = (const float*)d_in[8];
    // d_in[9] = mask (implemented as causal), d_in[10] = start_pos (0) — unused
    float* out = (float*)d_out;

    float *Qp, *Kp, *Vp, *Op, *aKp, *aVp;
    cudaGetSymbolAddress((void**)&Qp,  g_Q);
    cudaGetSymbolAddress((void**)&Kp,  g_K);
    cudaGetSymbolAddress((void**)&Vp,  g_V);
    cudaGetSymbolAddress((void**)&Op,  g_AO);
    cudaGetSymbolAddress((void**)&aKp, g_aK);
    cudaGetSymbolAddress((void**)&aVp, g_aV);

    cudaFuncSetAttribute(flash_kernel,
                         cudaFuncAttributeMaxDynamicSharedMemorySize, FLASH_SMEM);

    const int M = B_ * S_;          // 4096
    dim3 gbig(DIM_ / BN, M / BM);   // 32 x 32

    gemm_abt<<<gbig, 256>>>(x, wq, Qp, M, DIM_, DIM_);
    gemm_abt<<<gbig, 256>>>(x, wk, Kp, M, DIM_, DIM_);
    gemm_abt<<<gbig, 256>>>(x, wv, Vp, M, DIM_, DIM_);
    gemm_abt<<<dim3(DIM_ / BN, 1), 256>>>(adapter, wk, aKp, ADL_, DIM_, DIM_);
    gemm_abt<<<dim3(DIM_ / BN, 1), 256>>>(adapter, wv, aVp, ADL_, DIM_, DIM_);

    int ropeN = B_ * S_ * H_ * (D_ / 2);     // pairs
    rope_kernel<<<ropeN / 256, 256>>>(Qp, fcos, fsin, ropeN);
    rope_kernel<<<ropeN / 256, 256>>>(Kp, fcos, fsin, ropeN);

    flash_kernel<<<dim3(S_ / 64, H_, B_), 256, FLASH_SMEM>>>(Qp, Kp, Vp, Op);

    adapter_attn<<<(B_ * S_ * H_ * 32) / 256, 256>>>(Qp, aKp, aVp, gate, Op);

    gemm_abt<<<gbig, 256>>>(Op, wo, out, M, DIM_, DIM_);
}

// round 4
// speedup vs baseline: 1.8256x; 1.8256x over previous
#include <cuda_runtime.h>
#include <cuda_bf16.h>
#include <math.h>
#include <stdint.h>

// ---------------------------------------------------------------- constants
#define B_    2
#define S_    2048
#define H_    32
#define D_    128
#define DIM_  4096
#define ADL_  10
#define MROWS (B_ * S_)              // 4096
#define NELEM ((size_t)MROWS * DIM_) // 16,777,216

// ---------------------------------------------------------------- scratch
__device__ float g_Q [NELEM];
__device__ float g_K [NELEM];
__device__ float g_V [NELEM];
__device__ float g_AO[NELEM];
__device__ float g_aK[ADL_ * DIM_];
__device__ float g_aV[ADL_ * DIM_];

__device__ __nv_bfloat16 g_xh[NELEM],  g_xl[NELEM];
__device__ __nv_bfloat16 g_wqh[NELEM], g_wql[NELEM];
__device__ __nv_bfloat16 g_wkh[NELEM], g_wkl[NELEM];
__device__ __nv_bfloat16 g_wvh[NELEM], g_wvl[NELEM];
__device__ __nv_bfloat16 g_woh[NELEM], g_wol[NELEM];
__device__ __nv_bfloat16 g_oh[NELEM],  g_ol[NELEM];

// ---------------------------------------------------------------- PTX utils
__device__ __forceinline__ uint32_t smem_u32(const void* p) {
    uint32_t a;
    asm("{ .reg .u64 t; cvta.to.shared.u64 t, %1; cvt.u32.u64 %0, t; }"
        : "=r"(a) : "l"(p));
    return a;
}
#define CP_ASYNC16(dst, src) \
    asm volatile("cp.async.cg.shared.global [%0], [%1], 16;" \
                 :: "r"(dst), "l"(src) : "memory")
#define CP_COMMIT() asm volatile("cp.async.commit_group;" ::: "memory")
#define CP_WAIT(n)  asm volatile("cp.async.wait_group %0;" :: "n"(n) : "memory")

#define LDSM_X4(r0, r1, r2, r3, addr) \
    asm volatile("ldmatrix.sync.aligned.m8n8.x4.shared.b16 {%0,%1,%2,%3}, [%4];" \
                 : "=r"(r0), "=r"(r1), "=r"(r2), "=r"(r3) : "r"(addr))

#define MMA16816(c, a, b) \
    asm volatile("mma.sync.aligned.m16n8k16.row.col.f32.bf16.bf16.f32 " \
                 "{%0,%1,%2,%3}, {%4,%5,%6,%7}, {%8,%9}, {%0,%1,%2,%3};" \
                 : "+f"((c)[0]), "+f"((c)[1]), "+f"((c)[2]), "+f"((c)[3]) \
                 : "r"((a)[0]), "r"((a)[1]), "r"((a)[2]), "r"((a)[3]), \
                   "r"((b)[0]), "r"((b)[1]))

// ============================================================================
// bf16x3 HMMA GEMM: C[4096,4096] = (Ah+Al) * (Bh+Bl)^T, fp32 accumulate.
// CTA 128x128, BK=32, 8 warps (2x4), warp tile 64x32, cp.async 2-stage.
// smem tile: [128 rows][40 bf16] (80B stride, ldmatrix conflict-free).
// ============================================================================
#define GK_BK      32
#define GK_TILE_B  10240                 // 128 * 80
#define GK_STAGE_B (4 * GK_TILE_B)       // Ah, Al, Bh, Bl
#define GK_SMEM    (2 * GK_STAGE_B)      // 81920 B
#define GK_NIT     (DIM_ / GK_BK)        // 128

__device__ __forceinline__ void gk_fill(uint32_t sbase,
    const __nv_bfloat16* __restrict__ Ah, const __nv_bfloat16* __restrict__ Al,
    const __nv_bfloat16* __restrict__ Bh, const __nv_bfloat16* __restrict__ Bl,
    int rowBase, int colBase, int k0)
{
    const int tid = threadIdx.x;
#pragma unroll
    for (int i = 0; i < 2; i++) {
        int idx = tid + i * 256;          // 0..511
        int row = idx >> 2;               // 0..127
        int cg  = (idx & 3) * 8;          // bf16 col offset (16B groups)
        uint32_t doff = (uint32_t)(row * 80 + (idx & 3) * 16);
        size_t ga = (size_t)(rowBase + row) * DIM_ + k0 + cg;
        size_t gb = (size_t)(colBase + row) * DIM_ + k0 + cg;
        CP_ASYNC16(sbase + doff,                 Ah + ga);
        CP_ASYNC16(sbase + GK_TILE_B + doff,     Al + ga);
        CP_ASYNC16(sbase + 2 * GK_TILE_B + doff, Bh + gb);
        CP_ASYNC16(sbase + 3 * GK_TILE_B + doff, Bl + gb);
    }
}

__global__ __launch_bounds__(256, 1)
void mma_gemm(const __nv_bfloat16* __restrict__ Ah, const __nv_bfloat16* __restrict__ Al,
              const __nv_bfloat16* __restrict__ Bh, const __nv_bfloat16* __restrict__ Bl,
              float* __restrict__ C)
{
    extern __shared__ char sm[];
    const uint32_t base = smem_u32(sm);
    const int tid  = threadIdx.x;
    const int wid  = tid >> 5;
    const int lane = tid & 31;
    const int rowBase = blockIdx.y * 128;
    const int colBase = blockIdx.x * 128;
    const int wm = (wid & 1) * 64;        // warp m offset in tile
    const int wn = (wid >> 1) * 32;       // warp n offset in tile

    float acc[4][4][4];
#pragma unroll
    for (int mi = 0; mi < 4; mi++)
#pragma unroll
        for (int ni = 0; ni < 4; ni++)
#pragma unroll
            for (int q = 0; q < 4; q++) acc[mi][ni][q] = 0.f;

    gk_fill(base,              Ah, Al, Bh, Bl, rowBase, colBase, 0);
    CP_COMMIT();
    gk_fill(base + GK_STAGE_B, Ah, Al, Bh, Bl, rowBase, colBase, GK_BK);
    CP_COMMIT();

    // per-lane ldmatrix row/col offsets (bytes)
    const uint32_t aRow = (uint32_t)(wm + (lane & 15));
    const uint32_t bRow = (uint32_t)(wn + (lane & 15));
    const uint32_t kHalf = (uint32_t)((lane >> 4) * 16);   // 8 bf16 = 16B

    for (int it = 0; it < GK_NIT; it++) {
        if (it + 1 < GK_NIT) { CP_WAIT(1); } else { CP_WAIT(0); }
        __syncthreads();

        const uint32_t sb = base + (uint32_t)(it & 1) * GK_STAGE_B;

#pragma unroll
        for (int ks = 0; ks < 2; ks++) {
            const uint32_t kcol = (uint32_t)(ks * 32) + kHalf;   // bytes
            uint32_t ah[4][4], al[4][4], bh[4][2], bl[4][2];

#pragma unroll
            for (int mi = 0; mi < 4; mi++) {
                uint32_t off = (aRow + mi * 16) * 80 + kcol;
                LDSM_X4(ah[mi][0], ah[mi][1], ah[mi][2], ah[mi][3], sb + off);
                LDSM_X4(al[mi][0], al[mi][1], al[mi][2], al[mi][3],
                        sb + GK_TILE_B + off);
            }
#pragma unroll
            for (int np = 0; np < 2; np++) {
                uint32_t off = (bRow + np * 16) * 80 + kcol;
                uint32_t r0, r1, r2, r3;
                LDSM_X4(r0, r1, r2, r3, sb + 2 * GK_TILE_B + off);
                bh[2 * np][0] = r0; bh[2 * np][1] = r2;
                bh[2 * np + 1][0] = r1; bh[2 * np + 1][1] = r3;
                LDSM_X4(r0, r1, r2, r3, sb + 3 * GK_TILE_B + off);
                bl[2 * np][0] = r0; bl[2 * np][1] = r2;
                bl[2 * np + 1][0] = r1; bl[2 * np + 1][1] = r3;
            }
#pragma unroll
            for (int mi = 0; mi < 4; mi++)
#pragma unroll
                for (int ni = 0; ni < 4; ni++) {
                    MMA16816(acc[mi][ni], ah[mi], bh[ni]);
                    MMA16816(acc[mi][ni], ah[mi], bl[ni]);
                    MMA16816(acc[mi][ni], al[mi], bh[ni]);
                }
        }
        __syncthreads();

        if (it + 2 < GK_NIT) {
            gk_fill(base + (uint32_t)(it & 1) * GK_STAGE_B,
                    Ah, Al, Bh, Bl, rowBase, colBase, (it + 2) * GK_BK);
            CP_COMMIT();
        }
    }

    // epilogue
    const int r0 = rowBase + wm + (lane >> 2);
    const int c0 = colBase + wn + (lane & 3) * 2;
#pragma unroll
    for (int mi = 0; mi < 4; mi++)
#pragma unroll
        for (int ni = 0; ni < 4; ni++) {
            float* p = C + (size_t)(r0 + mi * 16) * DIM_ + c0 + ni * 8;
            *(float2*)p = make_float2(acc[mi][ni][0], acc[mi][ni][1]);
            *(float2*)(p + 8 * DIM_) = make_float2(acc[mi][ni][2], acc[mi][ni][3]);
        }
}

// ============================================================================
// fp32 -> (bf16 hi, bf16 lo) split
// ============================================================================
__global__ void split_bf16(const float* __restrict__ x,
                           __nv_bfloat16* __restrict__ hi,
                           __nv_bfloat16* __restrict__ lo)
{
    size_t i = (size_t)blockIdx.x * blockDim.x + threadIdx.x;
    float4 v = ((const float4*)x)[i];
    __nv_bfloat16 h0 = __float2bfloat16(v.x);
    __nv_bfloat16 h1 = __float2bfloat16(v.y);
    __nv_bfloat16 h2 = __float2bfloat16(v.z);
    __nv_bfloat16 h3 = __float2bfloat16(v.w);
    __nv_bfloat16 l0 = __float2bfloat16(v.x - __bfloat162float(h0));
    __nv_bfloat16 l1 = __float2bfloat16(v.y - __bfloat162float(h1));
    __nv_bfloat16 l2 = __float2bfloat16(v.z - __bfloat162float(h2));
    __nv_bfloat16 l3 = __float2bfloat16(v.w - __bfloat162float(h3));
    ((__nv_bfloat162*)hi)[2 * i]     = __nv_bfloat162(h0, h1);
    ((__nv_bfloat162*)hi)[2 * i + 1] = __nv_bfloat162(h2, h3);
    ((__nv_bfloat162*)lo)[2 * i]     = __nv_bfloat162(l0, l1);
    ((__nv_bfloat162*)lo)[2 * i + 1] = __nv_bfloat162(l2, l3);
}

// ============================================================================
// adapter GEMV: out[l, e] = sum_d A[l, d] * W[e, d]  (l < 10), fp32
// ============================================================================
__global__ __launch_bounds__(256)
void adapter_gemv(const float* __restrict__ A, const float* __restrict__ W,
                  float* __restrict__ out)
{
    int warp = (blockIdx.x * blockDim.x + threadIdx.x) >> 5;
    int lane = threadIdx.x & 31;
    int e0 = warp * 4;

    float acc[ADL_][4];
#pragma unroll
    for (int l = 0; l < ADL_; l++)
#pragma unroll
        for (int j = 0; j < 4; j++) acc[l][j] = 0.f;

    for (int d = lane * 4; d < DIM_; d += 128) {
        float4 w4[4];
#pragma unroll
        for (int j = 0; j < 4; j++)
            w4[j] = *(const float4*)(W + (size_t)(e0 + j) * DIM_ + d);
#pragma unroll
        for (int l = 0; l < ADL_; l++) {
            float4 a4 = *(const float4*)(A + (size_t)l * DIM_ + d);
#pragma unroll
            for (int j = 0; j < 4; j++) {
                acc[l][j] = fmaf(a4.x, w4[j].x, acc[l][j]);
                acc[l][j] = fmaf(a4.y, w4[j].y, acc[l][j]);
                acc[l][j] = fmaf(a4.z, w4[j].z, acc[l][j]);
                acc[l][j] = fmaf(a4.w, w4[j].w, acc[l][j]);
            }
        }
    }
#pragma unroll
    for (int l = 0; l < ADL_; l++)
#pragma unroll
        for (int j = 0; j < 4; j++) {
            float v = acc[l][j];
#pragma unroll
            for (int off = 16; off; off >>= 1)
                v += __shfl_xor_sync(0xffffffffu, v, off);
            if (lane == 0) out[l * DIM_ + e0 + j] = v;
        }
}

// ============================================================================
// RoPE (interleaved pairs), in-place on [B,S,H,D]
// ============================================================================
__global__ void rope_kernel(float* __restrict__ t,
                            const float* __restrict__ cosp,
                            const float* __restrict__ sinp, int total)
{
    int idx = blockIdx.x * blockDim.x + threadIdx.x;
    if (idx >= total) return;
    int i = idx & 63;
    int s = (idx >> 11) & (S_ - 1);
    float2 v = *(float2*)(t + (size_t)idx * 2);
    float c  = cosp[s * 64 + i];
    float sn = sinp[s * 64 + i];
    float2 o;
    o.x = v.x * c - v.y * sn;
    o.y = v.x * sn + v.y * c;
    *(float2*)(t + (size_t)idx * 2) = o;
}

// ============================================================================
// Causal flash attention (fp32 SIMT)
// ============================================================================
#define FQS 132
#define FPS 68
#define FLASH_SMEM ((3 * 64 * FQS + 64 * FPS) * 4)

__global__ __launch_bounds__(256, 1)
void flash_kernel(const float* __restrict__ Q, const float* __restrict__ K,
                  const float* __restrict__ V, float* __restrict__ O)
{
    extern __shared__ float fsm[];
    float* Qs = fsm;
    float* Ks = Qs + 64 * FQS;
    float* Vs = Ks + 64 * FQS;
    float* Ps = Vs + 64 * FQS;

    const int qt = blockIdx.x;
    const int h  = blockIdx.y;
    const int b  = blockIdx.z;
    const int tid = threadIdx.x;
    const int tx  = tid & 15;
    const int ty  = tid >> 4;

    const float* Qbase = Q + ((size_t)(b * S_) + qt * 64) * DIM_ + h * D_;

#pragma unroll
    for (int it = 0; it < 8; it++) {
        int idx = tid + it * 256;
        int r  = idx >> 5;
        int dq = (idx & 31) * 4;
        *(float4*)&Qs[r * FQS + dq] = *(const float4*)(Qbase + (size_t)r * DIM_ + dq);
    }

    float m[4], l[4], o[4][8];
#pragma unroll
    for (int i = 0; i < 4; i++) {
        m[i] = -1e30f; l[i] = 0.f;
#pragma unroll
        for (int c = 0; c < 8; c++) o[i][c] = 0.f;
    }
    const int qrow0 = qt * 64 + ty * 4;
    const float scale = 0.08838834764831845f;

    for (int kt = 0; kt <= qt; kt++) {
        __syncthreads();
        const float* Kbase = K + ((size_t)(b * S_) + kt * 64) * DIM_ + h * D_;
        const float* Vbase = V + ((size_t)(b * S_) + kt * 64) * DIM_ + h * D_;
#pragma unroll
        for (int it = 0; it < 8; it++) {
            int idx = tid + it * 256;
            int r  = idx >> 5;
            int dq = (idx & 31) * 4;
            *(float4*)&Ks[r * FQS + dq] = *(const float4*)(Kbase + (size_t)r * DIM_ + dq);
            *(float4*)&Vs[r * FQS + dq] = *(const float4*)(Vbase + (size_t)r * DIM_ + dq);
        }
        __syncthreads();

        float s[4][4];
#pragma unroll
        for (int i = 0; i < 4; i++)
#pragma unroll
            for (int j = 0; j < 4; j++) s[i][j] = 0.f;

#pragma unroll 8
        for (int d4 = 0; d4 < 32; d4++) {
            float4 qv[4], kv[4];
#pragma unroll
            for (int i = 0; i < 4; i++)
                qv[i] = *(const float4*)&Qs[(ty * 4 + i) * FQS + d4 * 4];
#pragma unroll
            for (int j = 0; j < 4; j++)
                kv[j] = *(const float4*)&Ks[(tx * 4 + j) * FQS + d4 * 4];
#pragma unroll
            for (int i = 0; i < 4; i++)
#pragma unroll
                for (int j = 0; j < 4; j++) {
                    s[i][j] = fmaf(qv[i].x, kv[j].x, s[i][j]);
                    s[i][j] = fmaf(qv[i].y, kv[j].y, s[i][j]);
                    s[i][j] = fmaf(qv[i].z, kv[j].z, s[i][j]);
                    s[i][j] = fmaf(qv[i].w, kv[j].w, s[i][j]);
                }
        }

        const bool diag = (kt == qt);
        float rscale[4];
#pragma unroll
        for (int i = 0; i < 4; i++) {
            int qg = qrow0 + i;
            float rmax = -1e30f;
#pragma unroll
            for (int j = 0; j < 4; j++) {
                float sv = s[i][j] * scale;
                if (diag && (kt * 64 + tx * 4 + j) > qg) sv = -1e30f;
                s[i][j] = sv;
                rmax = fmaxf(rmax, sv);
            }
#pragma unroll
            for (int off = 8; off; off >>= 1)
                rmax = fmaxf(rmax, __shfl_xor_sync(0xffffffffu, rmax, off, 16));
            float mnew = fmaxf(m[i], rmax);
            float sc   = __expf(m[i] - mnew);
            float rsum = 0.f;
#pragma unroll
            for (int j = 0; j < 4; j++) {
                float p = __expf(s[i][j] - mnew);
                s[i][j] = p;
                rsum += p;
            }
#pragma unroll
            for (int off = 8; off; off >>= 1)
                rsum += __shfl_xor_sync(0xffffffffu, rsum, off, 16);
            l[i] = l[i] * sc + rsum;
            m[i] = mnew;
            rscale[i] = sc;
            *(float4*)&Ps[(ty * 4 + i) * FPS + tx * 4] =
                make_float4(s[i][0], s[i][1], s[i][2], s[i][3]);
        }
        __syncwarp();

#pragma unroll
        for (int i = 0; i < 4; i++)
#pragma unroll
            for (int c = 0; c < 8; c++) o[i][c] *= rscale[i];

#pragma unroll 4
        for (int j4 = 0; j4 < 16; j4++) {
            float4 p4[4];
#pragma unroll
            for (int i = 0; i < 4; i++)
                p4[i] = *(const float4*)&Ps[(ty * 4 + i) * FPS + j4 * 4];
#pragma unroll
            for (int jj = 0; jj < 4; jj++) {
                float4 v0 = *(const float4*)&Vs[(j4 * 4 + jj) * FQS + tx * 8];
                float4 v1 = *(const float4*)&Vs[(j4 * 4 + jj) * FQS + tx * 8 + 4];
#pragma unroll
                for (int i = 0; i < 4; i++) {
                    float p = (jj == 0) ? p4[i].x : (jj == 1) ? p4[i].y :
                              (jj == 2) ? p4[i].z : p4[i].w;
                    o[i][0] = fmaf(p, v0.x, o[i][0]);
                    o[i][1] = fmaf(p, v0.y, o[i][1]);
                    o[i][2] = fmaf(p, v0.z, o[i][2]);
                    o[i][3] = fmaf(p, v0.w, o[i][3]);
                    o[i][4] = fmaf(p, v1.x, o[i][4]);
                    o[i][5] = fmaf(p, v1.y, o[i][5]);
                    o[i][6] = fmaf(p, v1.z, o[i][6]);
                    o[i][7] = fmaf(p, v1.w, o[i][7]);
                }
            }
        }
    }

    float* Obase = O + ((size_t)(b * S_) + qt * 64) * DIM_ + h * D_;
#pragma unroll
    for (int i = 0; i < 4; i++) {
        float inv = 1.0f / l[i];
        float* op = Obase + (size_t)(ty * 4 + i) * DIM_ + tx * 8;
        *(float4*)op       = make_float4(o[i][0] * inv, o[i][1] * inv,
                                         o[i][2] * inv, o[i][3] * inv);
        *(float4*)(op + 4) = make_float4(o[i][4] * inv, o[i][5] * inv,
                                         o[i][6] * inv, o[i][7] * inv);
    }
}

// ============================================================================
// Adapter attention (RMW into O)
// ============================================================================
__global__ void adapter_attn(const float* __restrict__ Q,
                             const float* __restrict__ aK,
                             const float* __restrict__ aV,
                             const float* __restrict__ gate,
                             float* __restrict__ O)
{
    int gw   = (blockIdx.x * blockDim.x + threadIdx.x) >> 5;
    int lane = threadIdx.x & 31;
    int h = gw & (H_ - 1);
    int s = (gw >> 5) & (S_ - 1);
    int b = gw >> 16;

    const float* q = Q + ((size_t)(b * S_ + s)) * DIM_ + h * D_;
    float4 qv = *(const float4*)(q + lane * 4);

    const float scale = 0.08838834764831845f;
    float sc[ADL_];
#pragma unroll
    for (int t = 0; t < ADL_; t++) {
        float4 kv = *(const float4*)(aK + t * DIM_ + h * D_ + lane * 4);
        float d = qv.x * kv.x + qv.y * kv.y + qv.z * kv.z + qv.w * kv.w;
#pragma unroll
        for (int off = 16; off; off >>= 1)
            d += __shfl_xor_sync(0xffffffffu, d, off);
        sc[t] = d * scale;
    }
    float mx = sc[0];
#pragma unroll
    for (int t = 1; t < ADL_; t++) mx = fmaxf(mx, sc[t]);
    float sum = 0.f;
#pragma unroll
    for (int t = 0; t < ADL_; t++) { sc[t] = __expf(sc[t] - mx); sum += sc[t]; }
    float inv = 1.0f / sum;
    float g = tanhf(gate[h]);

    float4 acc = make_float4(0.f, 0.f, 0.f, 0.f);
#pragma unroll
    for (int t = 0; t < ADL_; t++) {
        float4 vv = *(const float4*)(aV + t * DIM_ + h * D_ + lane * 4);
        float p = sc[t] * inv;
        acc.x = fmaf(p, vv.x, acc.x);
        acc.y = fmaf(p, vv.y, acc.y);
        acc.z = fmaf(p, vv.z, acc.z);
        acc.w = fmaf(p, vv.w, acc.w);
    }
    float* op = O + ((size_t)(b * S_ + s)) * DIM_ + h * D_ + lane * 4;
    float4 cur = *(float4*)op;
    cur.x += g * acc.x; cur.y += g * acc.y;
    cur.z += g * acc.z; cur.w += g * acc.w;
    *(float4*)op = cur;
}

// ============================================================================
// launch
// ============================================================================
extern "C" void kernel_launch(void* const* d_in, const int* in_sizes, int n_in,
                              void* d_out, int out_size)
{
    const float* x       = (const float*)d_in[0];
    const float* wq      = (const float*)d_in[1];
    const float* wk      = (const float*)d_in[2];
    const float* wv      = (const float*)d_in[3];
    const float* wo      = (const float*)d_in[4];
    const float* gate    = (const float*)d_in[5];
    const float* adapter = (const float*)d_in[6];
    const float* fcos    = (const float*)d_in[7];
    const float* fsin    = (const float*)d_in[8];
    float* out = (float*)d_out;

    float *Qp, *Kp, *Vp, *Op, *aKp, *aVp;
    cudaGetSymbolAddress((void**)&Qp,  g_Q);
    cudaGetSymbolAddress((void**)&Kp,  g_K);
    cudaGetSymbolAddress((void**)&Vp,  g_V);
    cudaGetSymbolAddress((void**)&Op,  g_AO);
    cudaGetSymbolAddress((void**)&aKp, g_aK);
    cudaGetSymbolAddress((void**)&aVp, g_aV);

    __nv_bfloat16 *xh, *xl, *wqh, *wql, *wkh, *wkl, *wvh, *wvl, *woh, *wol, *oh, *ol;
    cudaGetSymbolAddress((void**)&xh,  g_xh);  cudaGetSymbolAddress((void**)&xl,  g_xl);
    cudaGetSymbolAddress((void**)&wqh, g_wqh); cudaGetSymbolAddress((void**)&wql, g_wql);
    cudaGetSymbolAddress((void**)&wkh, g_wkh); cudaGetSymbolAddress((void**)&wkl, g_wkl);
    cudaGetSymbolAddress((void**)&wvh, g_wvh); cudaGetSymbolAddress((void**)&wvl, g_wvl);
    cudaGetSymbolAddress((void**)&woh, g_woh); cudaGetSymbolAddress((void**)&wol, g_wol);
    cudaGetSymbolAddress((void**)&oh,  g_oh);  cudaGetSymbolAddress((void**)&ol,  g_ol);

    cudaFuncSetAttribute(flash_kernel,
                         cudaFuncAttributeMaxDynamicSharedMemorySize, FLASH_SMEM);
    cudaFuncSetAttribute(mma_gemm,
                         cudaFuncAttributeMaxDynamicSharedMemorySize, GK_SMEM);

    const int splitBlocks = (int)(NELEM / 4 / 256);
    split_bf16<<<splitBlocks, 256>>>(x,  xh,  xl);
    split_bf16<<<splitBlocks, 256>>>(wq, wqh, wql);
    split_bf16<<<splitBlocks, 256>>>(wk, wkh, wkl);
    split_bf16<<<splitBlocks, 256>>>(wv, wvh, wvl);
    split_bf16<<<splitBlocks, 256>>>(wo, woh, wol);

    dim3 gg(DIM_ / 128, MROWS / 128);    // 32 x 32
    mma_gemm<<<gg, 256, GK_SMEM>>>(xh, xl, wqh, wql, Qp);
    mma_gemm<<<gg, 256, GK_SMEM>>>(xh, xl, wkh, wkl, Kp);
    mma_gemm<<<gg, 256, GK_SMEM>>>(xh, xl, wvh, wvl, Vp);

    adapter_gemv<<<128, 256>>>(adapter, wk, aKp);
    adapter_gemv<<<128, 256>>>(adapter, wv, aVp);

    int ropeN = B_ * S_ * H_ * (D_ / 2);
    rope_kernel<<<ropeN / 256, 256>>>(Qp, fcos, fsin, ropeN);
    rope_kernel<<<ropeN / 256, 256>>>(Kp, fcos, fsin, ropeN);

    flash_kernel<<<dim3(S_ / 64, H_, B_), 256, FLASH_SMEM>>>(Qp, Kp, Vp, Op);

    adapter_attn<<<(B_ * S_ * H_ * 32) / 256, 256>>>(Qp, aKp, aVp, gate, Op);

    split_bf16<<<splitBlocks, 256>>>(Op, oh, ol);
    mma_gemm<<<gg, 256, GK_SMEM>>>(oh, ol, woh, wol, out);
}

// round 5
// speedup vs baseline: 2.4744x; 1.3554x over previous
#include <cuda_runtime.h>
#include <cuda_bf16.h>
#include <math.h>
#include <stdint.h>

// ---------------------------------------------------------------- constants
#define B_    2
#define S_    2048
#define H_    32
#define D_    128
#define DIM_  4096
#define ADL_  10
#define MROWS (B_ * S_)
#define NELEM ((size_t)MROWS * DIM_)

// ---------------------------------------------------------------- scratch
__device__ float g_Q [NELEM];
__device__ float g_K [NELEM];
__device__ float g_V [NELEM];
__device__ float g_AO[NELEM];
__device__ float g_aK[ADL_ * DIM_];
__device__ float g_aV[ADL_ * DIM_];

__device__ __nv_bfloat16 g_xh[NELEM],  g_xl[NELEM];    // later reused as Vh/Vl
__device__ __nv_bfloat16 g_wqh[NELEM], g_wql[NELEM];   // later reused as Qh/Ql
__device__ __nv_bfloat16 g_wkh[NELEM], g_wkl[NELEM];   // later reused as Kh/Kl
__device__ __nv_bfloat16 g_wvh[NELEM], g_wvl[NELEM];
__device__ __nv_bfloat16 g_woh[NELEM], g_wol[NELEM];
__device__ __nv_bfloat16 g_oh[NELEM],  g_ol[NELEM];

// ---------------------------------------------------------------- PTX utils
__device__ __forceinline__ uint32_t smem_u32(const void* p) {
    uint32_t a;
    asm("{ .reg .u64 t; cvta.to.shared.u64 t, %1; cvt.u32.u64 %0, t; }"
        : "=r"(a) : "l"(p));
    return a;
}
#define CP_ASYNC16(dst, src) \
    asm volatile("cp.async.cg.shared.global [%0], [%1], 16;" \
                 :: "r"(dst), "l"(src) : "memory")
#define CP_COMMIT() asm volatile("cp.async.commit_group;" ::: "memory")
#define CP_WAIT(n)  asm volatile("cp.async.wait_group %0;" :: "n"(n) : "memory")

#define LDSM_X4(r0, r1, r2, r3, addr) \
    asm volatile("ldmatrix.sync.aligned.m8n8.x4.shared.b16 {%0,%1,%2,%3}, [%4];" \
                 : "=r"(r0), "=r"(r1), "=r"(r2), "=r"(r3) : "r"(addr))
#define LDSM_X4_T(r0, r1, r2, r3, addr) \
    asm volatile("ldmatrix.sync.aligned.m8n8.x4.trans.shared.b16 {%0,%1,%2,%3}, [%4];" \
                 : "=r"(r0), "=r"(r1), "=r"(r2), "=r"(r3) : "r"(addr))

#define MMA16816(c, a, b) \
    asm volatile("mma.sync.aligned.m16n8k16.row.col.f32.bf16.bf16.f32 " \
                 "{%0,%1,%2,%3}, {%4,%5,%6,%7}, {%8,%9}, {%0,%1,%2,%3};" \
                 : "+f"((c)[0]), "+f"((c)[1]), "+f"((c)[2]), "+f"((c)[3]) \
                 : "r"((a)[0]), "r"((a)[1]), "r"((a)[2]), "r"((a)[3]), \
                   "r"((b)[0]), "r"((b)[1]))

__device__ __forceinline__ uint32_t pack_bf16x2(float lo, float hi) {
    __nv_bfloat162 t = __floats2bfloat162_rn(lo, hi);
    return *(uint32_t*)&t;
}

// ============================================================================
// bf16x3 HMMA GEMM: 128x128 CTA tile, BK=32, 4-stage cp.async pipeline.
// ============================================================================
#define GK_BK      32
#define GK_TILE_B  10240
#define GK_STAGE_B (4 * GK_TILE_B)
#define GK_STAGES  4
#define GK_SMEM    (GK_STAGES * GK_STAGE_B)    // 163840
#define GK_NIT     (DIM_ / GK_BK)              // 128

__device__ __forceinline__ void gk_fill(uint32_t sbase,
    const __nv_bfloat16* __restrict__ Ah, const __nv_bfloat16* __restrict__ Al,
    const __nv_bfloat16* __restrict__ Bh, const __nv_bfloat16* __restrict__ Bl,
    int rowBase, int colBase, int k0)
{
    const int tid = threadIdx.x;
#pragma unroll
    for (int i = 0; i < 2; i++) {
        int idx = tid + i * 256;
        int row = idx >> 2;
        int cg  = (idx & 3) * 8;
        uint32_t doff = (uint32_t)(row * 80 + (idx & 3) * 16);
        size_t ga = (size_t)(rowBase + row) * DIM_ + k0 + cg;
        size_t gb = (size_t)(colBase + row) * DIM_ + k0 + cg;
        CP_ASYNC16(sbase + doff,                 Ah + ga);
        CP_ASYNC16(sbase + GK_TILE_B + doff,     Al + ga);
        CP_ASYNC16(sbase + 2 * GK_TILE_B + doff, Bh + gb);
        CP_ASYNC16(sbase + 3 * GK_TILE_B + doff, Bl + gb);
    }
}

__global__ __launch_bounds__(256, 1)
void mma_gemm(const __nv_bfloat16* __restrict__ Ah, const __nv_bfloat16* __restrict__ Al,
              const __nv_bfloat16* __restrict__ Bh, const __nv_bfloat16* __restrict__ Bl,
              float* __restrict__ C)
{
    extern __shared__ char sm[];
    const uint32_t base = smem_u32(sm);
    const int tid  = threadIdx.x;
    const int wid  = tid >> 5;
    const int lane = tid & 31;
    const int rowBase = blockIdx.y * 128;
    const int colBase = blockIdx.x * 128;
    const int wm = (wid & 1) * 64;
    const int wn = (wid >> 1) * 32;

    float acc[4][4][4];
#pragma unroll
    for (int mi = 0; mi < 4; mi++)
#pragma unroll
        for (int ni = 0; ni < 4; ni++)
#pragma unroll
            for (int q = 0; q < 4; q++) acc[mi][ni][q] = 0.f;

    gk_fill(base,                  Ah, Al, Bh, Bl, rowBase, colBase, 0);
    CP_COMMIT();
    gk_fill(base + GK_STAGE_B,     Ah, Al, Bh, Bl, rowBase, colBase, GK_BK);
    CP_COMMIT();
    gk_fill(base + 2 * GK_STAGE_B, Ah, Al, Bh, Bl, rowBase, colBase, 2 * GK_BK);
    CP_COMMIT();

    const uint32_t aRow = (uint32_t)(wm + (lane & 15));
    const uint32_t bRow = (uint32_t)(wn + (lane & 15));
    const uint32_t kHalf = (uint32_t)((lane >> 4) * 16);

    for (int it = 0; it < GK_NIT; it++) {
        CP_WAIT(2);
        __syncthreads();

        if (it + 3 < GK_NIT)
            gk_fill(base + (uint32_t)((it + 3) & 3) * GK_STAGE_B,
                    Ah, Al, Bh, Bl, rowBase, colBase, (it + 3) * GK_BK);
        CP_COMMIT();

        const uint32_t sb = base + (uint32_t)(it & 3) * GK_STAGE_B;

#pragma unroll
        for (int ks = 0; ks < 2; ks++) {
            const uint32_t kcol = (uint32_t)(ks * 32) + kHalf;
            uint32_t ah[4][4], al[4][4], bh[4][2], bl[4][2];

#pragma unroll
            for (int mi = 0; mi < 4; mi++) {
                uint32_t off = (aRow + mi * 16) * 80 + kcol;
                LDSM_X4(ah[mi][0], ah[mi][1], ah[mi][2], ah[mi][3], sb + off);
                LDSM_X4(al[mi][0], al[mi][1], al[mi][2], al[mi][3],
                        sb + GK_TILE_B + off);
            }
#pragma unroll
            for (int np = 0; np < 2; np++) {
                uint32_t off = (bRow + np * 16) * 80 + kcol;
                uint32_t r0, r1, r2, r3;
                LDSM_X4(r0, r1, r2, r3, sb + 2 * GK_TILE_B + off);
                bh[2 * np][0] = r0; bh[2 * np][1] = r2;
                bh[2 * np + 1][0] = r1; bh[2 * np + 1][1] = r3;
                LDSM_X4(r0, r1, r2, r3, sb + 3 * GK_TILE_B + off);
                bl[2 * np][0] = r0; bl[2 * np][1] = r2;
                bl[2 * np + 1][0] = r1; bl[2 * np + 1][1] = r3;
            }
#pragma unroll
            for (int mi = 0; mi < 4; mi++)
#pragma unroll
                for (int ni = 0; ni < 4; ni++) {
                    MMA16816(acc[mi][ni], ah[mi], bh[ni]);
                    MMA16816(acc[mi][ni], ah[mi], bl[ni]);
                    MMA16816(acc[mi][ni], al[mi], bh[ni]);
                }
        }
    }

    const int r0 = rowBase + wm + (lane >> 2);
    const int c0 = colBase + wn + (lane & 3) * 2;
#pragma unroll
    for (int mi = 0; mi < 4; mi++)
#pragma unroll
        for (int ni = 0; ni < 4; ni++) {
            float* p = C + (size_t)(r0 + mi * 16) * DIM_ + c0 + ni * 8;
            *(float2*)p = make_float2(acc[mi][ni][0], acc[mi][ni][1]);
            *(float2*)(p + 8 * DIM_) = make_float2(acc[mi][ni][2], acc[mi][ni][3]);
        }
}

// ============================================================================
// fp32 -> (bf16 hi, bf16 lo) split
// ============================================================================
__global__ void split_bf16(const float* __restrict__ x,
                           __nv_bfloat16* __restrict__ hi,
                           __nv_bfloat16* __restrict__ lo)
{
    size_t i = (size_t)blockIdx.x * blockDim.x + threadIdx.x;
    float4 v = ((const float4*)x)[i];
    __nv_bfloat16 h0 = __float2bfloat16(v.x);
    __nv_bfloat16 h1 = __float2bfloat16(v.y);
    __nv_bfloat16 h2 = __float2bfloat16(v.z);
    __nv_bfloat16 h3 = __float2bfloat16(v.w);
    __nv_bfloat16 l0 = __float2bfloat16(v.x - __bfloat162float(h0));
    __nv_bfloat16 l1 = __float2bfloat16(v.y - __bfloat162float(h1));
    __nv_bfloat16 l2 = __float2bfloat16(v.z - __bfloat162float(h2));
    __nv_bfloat16 l3 = __float2bfloat16(v.w - __bfloat162float(h3));
    ((__nv_bfloat162*)hi)[2 * i]     = __nv_bfloat162(h0, h1);
    ((__nv_bfloat162*)hi)[2 * i + 1] = __nv_bfloat162(h2, h3);
    ((__nv_bfloat162*)lo)[2 * i]     = __nv_bfloat162(l0, l1);
    ((__nv_bfloat162*)lo)[2 * i + 1] = __nv_bfloat162(l2, l3);
}

// ============================================================================
// RoPE + bf16 split: reads fp32 t, applies rope, optionally writes fp32 back,
// always writes bf16 hi/lo.
// ============================================================================
__global__ void rope_split(float* __restrict__ t,
                           __nv_bfloat16* __restrict__ th,
                           __nv_bfloat16* __restrict__ tl,
                           const float* __restrict__ cosp,
                           const float* __restrict__ sinp,
                           int total, int writef32)
{
    int idx = blockIdx.x * blockDim.x + threadIdx.x;
    if (idx >= total) return;
    int i = idx & 63;
    int s = (idx >> 11) & (S_ - 1);
    float2 v = *(float2*)(t + (size_t)idx * 2);
    float c  = cosp[s * 64 + i];
    float sn = sinp[s * 64 + i];
    float ox = v.x * c - v.y * sn;
    float oy = v.x * sn + v.y * c;
    if (writef32) *(float2*)(t + (size_t)idx * 2) = make_float2(ox, oy);
    __nv_bfloat16 h0 = __float2bfloat16(ox);
    __nv_bfloat16 h1 = __float2bfloat16(oy);
    __nv_bfloat16 l0 = __float2bfloat16(ox - __bfloat162float(h0));
    __nv_bfloat16 l1 = __float2bfloat16(oy - __bfloat162float(h1));
    ((__nv_bfloat162*)th)[idx] = __nv_bfloat162(h0, h1);
    ((__nv_bfloat162*)tl)[idx] = __nv_bfloat162(l0, l1);
}

// ============================================================================
// Tensor-core causal flash attention (bf16x3 everywhere, fp32 softmax).
// CTA: 128 q rows, 8 warps (m16 each); kv tiles of 64, double-buffered.
// ============================================================================
#define FRSTR   272
#define FQ_TILE (128 * FRSTR)            // 34816
#define FK_TILE (64 * FRSTR)             // 17408
#define FSTAGE  (4 * FK_TILE)            // Kh,Kl,Vh,Vl = 69632
#define FLASH_SMEM (2 * FQ_TILE + 2 * FSTAGE)   // 208896

__device__ __forceinline__ void fkv_fill(uint32_t sdst,
    const __nv_bfloat16* __restrict__ Kh, const __nv_bfloat16* __restrict__ Kl,
    const __nv_bfloat16* __restrict__ Vh, const __nv_bfloat16* __restrict__ Vl,
    int b, int h, int kv0)
{
    const int tid = threadIdx.x;
    const size_t gbase = ((size_t)(b * S_) + kv0) * DIM_ + h * D_;
#pragma unroll
    for (int i = 0; i < 16; i++) {
        int idx = tid + i * 256;
        int arr = idx >> 10;
        int rem = idx & 1023;
        int row = rem >> 4;
        int ch  = rem & 15;
        const __nv_bfloat16* src =
            (arr == 0) ? Kh : (arr == 1) ? Kl : (arr == 2) ? Vh : Vl;
        CP_ASYNC16(sdst + arr * FK_TILE + row * FRSTR + ch * 16,
                   src + gbase + (size_t)row * DIM_ + ch * 8);
    }
}

__global__ __launch_bounds__(256, 1)
void flash_mma(const __nv_bfloat16* __restrict__ Qh_g, const __nv_bfloat16* __restrict__ Ql_g,
               const __nv_bfloat16* __restrict__ Kh_g, const __nv_bfloat16* __restrict__ Kl_g,
               const __nv_bfloat16* __restrict__ Vh_g, const __nv_bfloat16* __restrict__ Vl_g,
               float* __restrict__ O)
{
    extern __shared__ char sm[];
    const uint32_t base = smem_u32(sm);
    const int tid  = threadIdx.x;
    const int wid  = tid >> 5;
    const int lane = tid & 31;
    const int qt = blockIdx.x, h = blockIdx.y, b = blockIdx.z;
    const int nkt = 2 * qt + 2;

    const uint32_t sQh = base;               // Ql at +FQ_TILE
    const uint32_t sKV = base + 2 * FQ_TILE; // stage*(FSTAGE): Kh,Kl,Vh,Vl

    // Q tile fill (128 rows)
    {
        size_t gq = ((size_t)(b * S_) + qt * 128) * DIM_ + h * D_;
#pragma unroll
        for (int i = 0; i < 8; i++) {
            int idx = tid + i * 256;
            int row = idx >> 4, ch = idx & 15;
            uint32_t d = row * FRSTR + ch * 16;
            size_t src = gq + (size_t)row * DIM_ + ch * 8;
            CP_ASYNC16(sQh + d,           Qh_g + src);
            CP_ASYNC16(sQh + FQ_TILE + d, Ql_g + src);
        }
    }
    fkv_fill(sKV, Kh_g, Kl_g, Vh_g, Vl_g, b, h, 0);
    CP_COMMIT();

    const int q0  = qt * 128 + wid * 16;
    const int qg0 = q0 + (lane >> 2);
    const int qg1 = qg0 + 8;
    const float scl = 0.08838834764831845f;

    float m0 = -1e30f, m1 = -1e30f, l0 = 0.f, l1 = 0.f;
    float o[16][4];
#pragma unroll
    for (int d = 0; d < 16; d++)
#pragma unroll
        for (int q = 0; q < 4; q++) o[d][q] = 0.f;

    for (int kt = 0; kt < nkt; kt++) {
        if (kt + 1 < nkt)
            fkv_fill(sKV + ((kt + 1) & 1) * FSTAGE,
                     Kh_g, Kl_g, Vh_g, Vl_g, b, h, (kt + 1) * 64);
        CP_COMMIT();
        CP_WAIT(1);
        __syncthreads();

        const uint32_t st = sKV + (uint32_t)(kt & 1) * FSTAGE;
        const int kv0 = kt * 64;

        if (kv0 <= q0 + 15) {
            // ---- S = Q K^T (bf16x3) ----
            float sa[8][4];
#pragma unroll
            for (int n8 = 0; n8 < 8; n8++)
#pragma unroll
                for (int q = 0; q < 4; q++) sa[n8][q] = 0.f;

            const uint32_t qrow = (uint32_t)(wid * 16 + (lane & 15));
            const uint32_t klrow = (uint32_t)(lane & 15);
            const uint32_t kh16 = (uint32_t)((lane >> 4) * 16);

#pragma unroll
            for (int ch = 0; ch < 8; ch++) {
                uint32_t qa = sQh + qrow * FRSTR + ch * 32 + kh16;
                uint32_t qh[4], ql[4];
                LDSM_X4(qh[0], qh[1], qh[2], qh[3], qa);
                LDSM_X4(ql[0], ql[1], ql[2], ql[3], qa + FQ_TILE);
#pragma unroll
                for (int nb = 0; nb < 4; nb++) {
                    uint32_t ka = st + (klrow + nb * 16) * FRSTR + ch * 32 + kh16;
                    uint32_t r0, r1, r2, r3, t0, t1, t2, t3;
                    LDSM_X4(r0, r1, r2, r3, ka);                // Kh
                    LDSM_X4(t0, t1, t2, t3, ka + FK_TILE);      // Kl
                    uint32_t kb0[2] = {r0, r2}, kb1[2] = {r1, r3};
                    uint32_t lb0[2] = {t0, t2}, lb1[2] = {t1, t3};
                    MMA16816(sa[2 * nb],     qh, kb0);
                    MMA16816(sa[2 * nb],     qh, lb0);
                    MMA16816(sa[2 * nb],     ql, kb0);
                    MMA16816(sa[2 * nb + 1], qh, kb1);
                    MMA16816(sa[2 * nb + 1], qh, lb1);
                    MMA16816(sa[2 * nb + 1], ql, kb1);
                }
            }

            // ---- mask + online softmax ----
            float rmax0 = -1e30f, rmax1 = -1e30f;
            const int kvb = kv0 + (lane & 3) * 2;
#pragma unroll
            for (int n8 = 0; n8 < 8; n8++) {
                int kvc = kvb + n8 * 8;
                float s0 = sa[n8][0] * scl, s1 = sa[n8][1] * scl;
                float s2 = sa[n8][2] * scl, s3 = sa[n8][3] * scl;
                if (kvc     > qg0) s0 = -1e30f;
                if (kvc + 1 > qg0) s1 = -1e30f;
                if (kvc     > qg1) s2 = -1e30f;
                if (kvc + 1 > qg1) s3 = -1e30f;
                sa[n8][0] = s0; sa[n8][1] = s1; sa[n8][2] = s2; sa[n8][3] = s3;
                rmax0 = fmaxf(rmax0, fmaxf(s0, s1));
                rmax1 = fmaxf(rmax1, fmaxf(s2, s3));
            }
            rmax0 = fmaxf(rmax0, __shfl_xor_sync(0xffffffffu, rmax0, 1));
            rmax0 = fmaxf(rmax0, __shfl_xor_sync(0xffffffffu, rmax0, 2));
            rmax1 = fmaxf(rmax1, __shfl_xor_sync(0xffffffffu, rmax1, 1));
            rmax1 = fmaxf(rmax1, __shfl_xor_sync(0xffffffffu, rmax1, 2));

            float mn0 = fmaxf(m0, rmax0), mn1 = fmaxf(m1, rmax1);
            float sc0 = __expf(m0 - mn0), sc1 = __expf(m1 - mn1);
            m0 = mn0; m1 = mn1;

            uint32_t ph[16], pl[16];
            float rs0 = 0.f, rs1 = 0.f;
#pragma unroll
            for (int n8 = 0; n8 < 8; n8++) {
                float p0 = __expf(sa[n8][0] - mn0);
                float p1 = __expf(sa[n8][1] - mn0);
                float p2 = __expf(sa[n8][2] - mn1);
                float p3 = __expf(sa[n8][3] - mn1);
                rs0 += p0 + p1; rs1 += p2 + p3;
                float h0 = __bfloat162float(__float2bfloat16(p0));
                float h1 = __bfloat162float(__float2bfloat16(p1));
                float h2 = __bfloat162float(__float2bfloat16(p2));
                float h3 = __bfloat162float(__float2bfloat16(p3));
                ph[2 * n8]     = pack_bf16x2(h0, h1);
                ph[2 * n8 + 1] = pack_bf16x2(h2, h3);
                pl[2 * n8]     = pack_bf16x2(p0 - h0, p1 - h1);
                pl[2 * n8 + 1] = pack_bf16x2(p2 - h2, p3 - h3);
            }
            rs0 += __shfl_xor_sync(0xffffffffu, rs0, 1);
            rs0 += __shfl_xor_sync(0xffffffffu, rs0, 2);
            rs1 += __shfl_xor_sync(0xffffffffu, rs1, 1);
            rs1 += __shfl_xor_sync(0xffffffffu, rs1, 2);
            l0 = l0 * sc0 + rs0;
            l1 = l1 * sc1 + rs1;

#pragma unroll
            for (int d = 0; d < 16; d++) {
                o[d][0] *= sc0; o[d][1] *= sc0;
                o[d][2] *= sc1; o[d][3] *= sc1;
            }

            // ---- O += P V (bf16x3) ----
#pragma unroll
            for (int j = 0; j < 4; j++) {
                uint32_t ah[4] = {ph[4*j], ph[4*j+1], ph[4*j+2], ph[4*j+3]};
                uint32_t al[4] = {pl[4*j], pl[4*j+1], pl[4*j+2], pl[4*j+3]};
#pragma unroll
                for (int nb = 0; nb < 8; nb++) {
                    uint32_t va = st + 2 * FK_TILE +
                                  (uint32_t)(j * 16 + (lane & 15)) * FRSTR +
                                  nb * 32 + kh16;
                    uint32_t r0, r1, r2, r3, t0, t1, t2, t3;
                    LDSM_X4_T(r0, r1, r2, r3, va);              // Vh
                    LDSM_X4_T(t0, t1, t2, t3, va + FK_TILE);    // Vl
                    uint32_t vh0[2] = {r0, r1}, vh1[2] = {r2, r3};
                    uint32_t vl0[2] = {t0, t1}, vl1[2] = {t2, t3};
                    MMA16816(o[2 * nb],     ah, vh0);
                    MMA16816(o[2 * nb],     ah, vl0);
                    MMA16816(o[2 * nb],     al, vh0);
                    MMA16816(o[2 * nb + 1], ah, vh1);
                    MMA16816(o[2 * nb + 1], ah, vl1);
                    MMA16816(o[2 * nb + 1], al, vh1);
                }
            }
        }
        __syncthreads();
    }

    // epilogue
    const float inv0 = 1.0f / l0, inv1 = 1.0f / l1;
    float* O0 = O + ((size_t)(b * S_) + qg0) * DIM_ + h * D_ + (lane & 3) * 2;
    float* O1 = O + ((size_t)(b * S_) + qg1) * DIM_ + h * D_ + (lane & 3) * 2;
#pragma unroll
    for (int d = 0; d < 16; d++) {
        *(float2*)(O0 + d * 8) = make_float2(o[d][0] * inv0, o[d][1] * inv0);
        *(float2*)(O1 + d * 8) = make_float2(o[d][2] * inv1, o[d][3] * inv1);
    }
}

// ============================================================================
// adapter GEMV (fp32): out[l, e] = sum_d A[l, d] * W[e, d]
// ============================================================================
__global__ __launch_bounds__(256)
void adapter_gemv(const float* __restrict__ A, const float* __restrict__ W,
                  float* __restrict__ out)
{
    int warp = (blockIdx.x * blockDim.x + threadIdx.x) >> 5;
    int lane = threadIdx.x & 31;
    int e0 = warp * 4;

    float acc[ADL_][4];
#pragma unroll
    for (int l = 0; l < ADL_; l++)
#pragma unroll
        for (int j = 0; j < 4; j++) acc[l][j] = 0.f;

    for (int d = lane * 4; d < DIM_; d += 128) {
        float4 w4[4];
#pragma unroll
        for (int j = 0; j < 4; j++)
            w4[j] = *(const float4*)(W + (size_t)(e0 + j) * DIM_ + d);
#pragma unroll
        for (int l = 0; l < ADL_; l++) {
            float4 a4 = *(const float4*)(A + (size_t)l * DIM_ + d);
#pragma unroll
            for (int j = 0; j < 4; j++) {
                acc[l][j] = fmaf(a4.x, w4[j].x, acc[l][j]);
                acc[l][j] = fmaf(a4.y, w4[j].y, acc[l][j]);
                acc[l][j] = fmaf(a4.z, w4[j].z, acc[l][j]);
                acc[l][j] = fmaf(a4.w, w4[j].w, acc[l][j]);
            }
        }
    }
#pragma unroll
    for (int l = 0; l < ADL_; l++)
#pragma unroll
        for (int j = 0; j < 4; j++) {
            float v = acc[l][j];
#pragma unroll
            for (int off = 16; off; off >>= 1)
                v += __shfl_xor_sync(0xffffffffu, v, off);
            if (lane == 0) out[l * DIM_ + e0 + j] = v;
        }
}

// ============================================================================
// Adapter attention (RMW into O)
// ============================================================================
__global__ void adapter_attn(const float* __restrict__ Q,
                             const float* __restrict__ aK,
                             const float* __restrict__ aV,
                             const float* __restrict__ gate,
                             float* __restrict__ O)
{
    int gw   = (blockIdx.x * blockDim.x + threadIdx.x) >> 5;
    int lane = threadIdx.x & 31;
    int h = gw & (H_ - 1);
    int s = (gw >> 5) & (S_ - 1);
    int b = gw >> 16;

    const float* q = Q + ((size_t)(b * S_ + s)) * DIM_ + h * D_;
    float4 qv = *(const float4*)(q + lane * 4);

    const float scale = 0.08838834764831845f;
    float sc[ADL_];
#pragma unroll
    for (int t = 0; t < ADL_; t++) {
        float4 kv = *(const float4*)(aK + t * DIM_ + h * D_ + lane * 4);
        float d = qv.x * kv.x + qv.y * kv.y + qv.z * kv.z + qv.w * kv.w;
#pragma unroll
        for (int off = 16; off; off >>= 1)
            d += __shfl_xor_sync(0xffffffffu, d, off);
        sc[t] = d * scale;
    }
    float mx = sc[0];
#pragma unroll
    for (int t = 1; t < ADL_; t++) mx = fmaxf(mx, sc[t]);
    float sum = 0.f;
#pragma unroll
    for (int t = 0; t < ADL_; t++) { sc[t] = __expf(sc[t] - mx); sum += sc[t]; }
    float inv = 1.0f / sum;
    float g = tanhf(gate[h]);

    float4 acc = make_float4(0.f, 0.f, 0.f, 0.f);
#pragma unroll
    for (int t = 0; t < ADL_; t++) {
        float4 vv = *(const float4*)(aV + t * DIM_ + h * D_ + lane * 4);
        float p = sc[t] * inv;
        acc.x = fmaf(p, vv.x, acc.x);
        acc.y = fmaf(p, vv.y, acc.y);
        acc.z = fmaf(p, vv.z, acc.z);
        acc.w = fmaf(p, vv.w, acc.w);
    }
    float* op = O + ((size_t)(b * S_ + s)) * DIM_ + h * D_ + lane * 4;
    float4 cur = *(float4*)op;
    cur.x += g * acc.x; cur.y += g * acc.y;
    cur.z += g * acc.z; cur.w += g * acc.w;
    *(float4*)op = cur;
}

// ============================================================================
// launch
// ============================================================================
extern "C" void kernel_launch(void* const* d_in, const int* in_sizes, int n_in,
                              void* d_out, int out_size)
{
    const float* x       = (const float*)d_in[0];
    const float* wq      = (const float*)d_in[1];
    const float* wk      = (const float*)d_in[2];
    const float* wv      = (const float*)d_in[3];
    const float* wo      = (const float*)d_in[4];
    const float* gate    = (const float*)d_in[5];
    const float* adapter = (const float*)d_in[6];
    const float* fcos    = (const float*)d_in[7];
    const float* fsin    = (const float*)d_in[8];
    float* out = (float*)d_out;

    float *Qp, *Kp, *Vp, *Op, *aKp, *aVp;
    cudaGetSymbolAddress((void**)&Qp,  g_Q);
    cudaGetSymbolAddress((void**)&Kp,  g_K);
    cudaGetSymbolAddress((void**)&Vp,  g_V);
    cudaGetSymbolAddress((void**)&Op,  g_AO);
    cudaGetSymbolAddress((void**)&aKp, g_aK);
    cudaGetSymbolAddress((void**)&aVp, g_aV);

    __nv_bfloat16 *xh, *xl, *wqh, *wql, *wkh, *wkl, *wvh, *wvl, *woh, *wol, *oh, *ol;
    cudaGetSymbolAddress((void**)&xh,  g_xh);  cudaGetSymbolAddress((void**)&xl,  g_xl);
    cudaGetSymbolAddress((void**)&wqh, g_wqh); cudaGetSymbolAddress((void**)&wql, g_wql);
    cudaGetSymbolAddress((void**)&wkh, g_wkh); cudaGetSymbolAddress((void**)&wkl, g_wkl);
    cudaGetSymbolAddress((void**)&wvh, g_wvh); cudaGetSymbolAddress((void**)&wvl, g_wvl);
    cudaGetSymbolAddress((void**)&woh, g_woh); cudaGetSymbolAddress((void**)&wol, g_wol);
    cudaGetSymbolAddress((void**)&oh,  g_oh);  cudaGetSymbolAddress((void**)&ol,  g_ol);

    cudaFuncSetAttribute(mma_gemm,
                         cudaFuncAttributeMaxDynamicSharedMemorySize, GK_SMEM);
    cudaFuncSetAttribute(flash_mma,
                         cudaFuncAttributeMaxDynamicSharedMemorySize, FLASH_SMEM);

    const int splitBlocks = (int)(NELEM / 4 / 256);
    dim3 gg(DIM_ / 128, MROWS / 128);

    split_bf16<<<splitBlocks, 256>>>(x,  xh,  xl);       // 1
    split_bf16<<<splitBlocks, 256>>>(wq, wqh, wql);      // 2
    split_bf16<<<splitBlocks, 256>>>(wk, wkh, wkl);      // 3
    split_bf16<<<splitBlocks, 256>>>(wv, wvh, wvl);      // 4
    adapter_gemv<<<128, 256>>>(adapter, wk, aKp);        // 5
    mma_gemm<<<gg, 256, GK_SMEM>>>(xh, xl, wqh, wql, Qp);   // 6 (profiled)
    adapter_gemv<<<128, 256>>>(adapter, wv, aVp);
    mma_gemm<<<gg, 256, GK_SMEM>>>(xh, xl, wkh, wkl, Kp);
    mma_gemm<<<gg, 256, GK_SMEM>>>(xh, xl, wvh, wvl, Vp);
    split_bf16<<<splitBlocks, 256>>>(wo, woh, wol);

    // rope + split (Q keeps fp32 for adapter attention; K bf16-only)
    int ropeN = B_ * S_ * H_ * (D_ / 2);
    rope_split<<<ropeN / 256, 256>>>(Qp, wqh, wql, fcos, fsin, ropeN, 1);
    rope_split<<<ropeN / 256, 256>>>(Kp, wkh, wkl, fcos, fsin, ropeN, 0);
    split_bf16<<<splitBlocks, 256>>>(Vp, xh, xl);        // Vh/Vl

    flash_mma<<<dim3(S_ / 128, H_, B_), 256, FLASH_SMEM>>>(
        wqh, wql, wkh, wkl, xh, xl, Op);

    adapter_attn<<<(B_ * S_ * H_ * 32) / 256, 256>>>(Qp, aKp, aVp, gate, Op);

    split_bf16<<<splitBlocks, 256>>>(Op, oh, ol);
    mma_gemm<<<gg, 256, GK_SMEM>>>(oh, ol, woh, wol, out);
}